// round 1
// baseline (speedup 1.0000x reference)
#include <cuda_runtime.h>
#include <math.h>

#define TK 16

// ---------------- scratch (device globals: no allocation allowed) ----------------
__device__ __align__(16) float g_hen[64 * 64];
__device__ __align__(16) float g_hde[64 * 64];
__device__ __align__(16) float g_buf1[64 * 200];
__device__ __align__(16) float g_buf2[64 * 100];
__device__ __align__(16) float g_lat [64 * 10];
__device__ __align__(16) float g_buf3[64 * 100];
__device__ __align__(16) float g_buf4[64 * 200];
__device__ __align__(16) float g_part[8 * 64 * 200];

// ---------------- hypernet first two layers: h = tanh(tanh(mu W0^T + b0) W1^T + b1) ----------------
__global__ __launch_bounds__(256) void hyper_kernel(
    const float* __restrict__ mu,
    const float* __restrict__ enW0, const float* __restrict__ enb0,
    const float* __restrict__ enW1, const float* __restrict__ enb1,
    const float* __restrict__ deW0, const float* __restrict__ deb0,
    const float* __restrict__ deW1, const float* __restrict__ deb1)
{
    const float* W0; const float* b0; const float* W1; const float* b1; float* H;
    if (blockIdx.x == 0) { W0 = enW0; b0 = enb0; W1 = enW1; b1 = enb1; H = g_hen; }
    else                 { W0 = deW0; b0 = deb0; W1 = deW1; b1 = deb1; H = g_hde; }

    __shared__ float mus[64 * 4];
    __shared__ float h1[64][65];
    int tid = threadIdx.x;
    if (tid < 256) mus[tid] = mu[tid];
    __syncthreads();

    for (int idx = tid; idx < 4096; idx += 256) {
        int b = idx >> 6, o = idx & 63;
        float s = b0[o];
#pragma unroll
        for (int j = 0; j < 4; j++) s += mus[b * 4 + j] * W0[o * 4 + j];
        h1[b][o] = tanhf(s);
    }
    __syncthreads();
    for (int idx = tid; idx < 4096; idx += 256) {
        int b = idx >> 6, o = idx & 63;
        float s = b1[o];
#pragma unroll
        for (int k = 0; k < 64; k++) s += h1[b][k] * W1[o * 64 + k];
        H[b * 64 + o] = tanhf(s);
    }
}

// ---------------- fused hyper-FC layer ----------------
// For output channel c (blockIdx.x), K-split (blockIdx.y):
//   G[b,k]   = sum_{i in split} x'[b,i] * W2[row(c,i), k]    (x'[b,ni] = 1 covers the bias row)
//   t[b]     = sum_{i in split} x'[b,i] * b2[row(c,i)]
//   out[b,c] = sum_k h[b,k]*G[b,k] + t[b]      (optional tanh; splits write partial buffers)
__global__ __launch_bounds__(256) void fc_kernel(
    const float* __restrict__ x, const float* __restrict__ W2, const float* __restrict__ b2,
    const float* __restrict__ h, float* __restrict__ out, float* __restrict__ out2,
    int ni, int no, long off, int nsplit, int do_tanh)
{
    const int c     = blockIdx.x;
    const int split = blockIdx.y;
    const int K     = ni + 1;                       // +1: bias row folded into K
    const int len   = (K + nsplit - 1) / nsplit;
    const int kbeg  = split * len;
    const int kend  = min(kbeg + len, K);

    const int tid = threadIdx.x;
    const int tx = tid & 15, ty = tid >> 4;         // 16x16 thread grid, 4x4 tiles
    const int bb = tid & 63, qq = tid >> 6;         // bias-dot mapping

    __shared__ __align__(16) float xs[TK][68];      // xs[ii][b]
    __shared__ __align__(16) float ws[TK][68];      // ws[ii][k]
    __shared__ float b2s[TK];
    __shared__ float red[64][17];
    __shared__ float tbuf[4][64];

    float acc[4][4] = {};
    float tp = 0.f;

    const long wbase = off + (long)c * ni;          // weight rows for this channel
    const long brow  = off + (long)ni * no + c;     // bias row for this channel

    for (int i0 = kbeg; i0 < kend; i0 += TK) {
        __syncthreads();
        // load W2 tile (+bias column values)
#pragma unroll
        for (int e = tid; e < TK * 64; e += 256) {
            int ii = e >> 6, k = e & 63;
            int gi = i0 + ii;
            float v = 0.f;
            if (gi < kend) {
                long row = (gi < ni) ? (wbase + gi) : brow;
                v = W2[row * 64 + k];
            }
            ws[ii][k] = v;
        }
        if (tid < TK) {
            int gi = i0 + tid;
            float v = 0.f;
            if (gi < kend) {
                long row = (gi < ni) ? (wbase + gi) : brow;
                v = b2[row];
            }
            b2s[tid] = v;
        }
        // load x tile transposed: xs[ii][b]
#pragma unroll
        for (int e = tid; e < TK * 64; e += 256) {
            int b = e >> 4, ii = e & 15;
            int gi = i0 + ii;
            float v = 0.f;
            if (gi < kend) v = (gi < ni) ? x[b * ni + gi] : 1.0f;
            xs[ii][b] = v;
        }
        __syncthreads();

        // main 64x64 GEMM micro-tile
#pragma unroll
        for (int ii = 0; ii < TK; ii++) {
            const float4 xv = *(const float4*)&xs[ii][ty * 4];
            const float4 wv = *(const float4*)&ws[ii][tx * 4];
            acc[0][0] += xv.x * wv.x; acc[0][1] += xv.x * wv.y; acc[0][2] += xv.x * wv.z; acc[0][3] += xv.x * wv.w;
            acc[1][0] += xv.y * wv.x; acc[1][1] += xv.y * wv.y; acc[1][2] += xv.y * wv.z; acc[1][3] += xv.y * wv.w;
            acc[2][0] += xv.z * wv.x; acc[2][1] += xv.z * wv.y; acc[2][2] += xv.z * wv.z; acc[2][3] += xv.z * wv.w;
            acc[3][0] += xv.w * wv.x; acc[3][1] += xv.w * wv.y; acc[3][2] += xv.w * wv.z; acc[3][3] += xv.w * wv.w;
        }
        // bias dot: thread handles b = tid&63, quarter qq of the ii range
#pragma unroll
        for (int q = 0; q < 4; q++) {
            int ii = qq * 4 + q;
            tp += xs[ii][bb] * b2s[ii];
        }
    }

    // fold with h: out[b,c] = sum_k h[b,k]*G[b,k]
#pragma unroll
    for (int j = 0; j < 4; j++) {
        int bj = ty * 4 + j;
        const float4 hh = *(const float4*)(h + bj * 64 + tx * 4);
        red[bj][tx] = acc[j][0] * hh.x + acc[j][1] * hh.y + acc[j][2] * hh.z + acc[j][3] * hh.w;
    }
    tbuf[qq][bb] = tp;
    __syncthreads();

    if (tid < 64) {
        int b = tid;
        float v = 0.f;
#pragma unroll
        for (int t2 = 0; t2 < 16; t2++) v += red[b][t2];
        v += tbuf[0][b] + tbuf[1][b] + tbuf[2][b] + tbuf[3][b];
        if (do_tanh) v = tanhf(v);
        float* o = out + ((nsplit > 1) ? (long)split * 64 * no : 0L);
        o[b * no + c] = v;
        if (out2) out2[b * no + c] = v;
    }
}

// sum K-split partials (deterministic, no atomics)
__global__ void reduce_kernel(const float* __restrict__ part, float* __restrict__ out, int n, int s)
{
    int i = blockIdx.x * blockDim.x + threadIdx.x;
    if (i < n) {
        float v = 0.f;
        for (int j = 0; j < s; j++) v += part[(long)j * n + i];
        out[i] = v;
    }
}

extern "C" void kernel_launch(void* const* d_in, const int* in_sizes, int n_in,
                              void* d_out, int out_size)
{
    const float* z    = (const float*)d_in[0];
    const float* mu   = (const float*)d_in[1];
    const float* enW0 = (const float*)d_in[2];
    const float* enb0 = (const float*)d_in[3];
    const float* enW1 = (const float*)d_in[4];
    const float* enb1 = (const float*)d_in[5];
    const float* enW2 = (const float*)d_in[6];
    const float* enb2 = (const float*)d_in[7];
    const float* deW0 = (const float*)d_in[8];
    const float* deb0 = (const float*)d_in[9];
    const float* deW1 = (const float*)d_in[10];
    const float* deb1 = (const float*)d_in[11];
    const float* deW2 = (const float*)d_in[12];
    const float* deb2 = (const float*)d_in[13];
    float* out = (float*)d_out;

    float *hen, *hde, *buf1, *buf2, *lat, *buf3, *buf4, *part;
    cudaGetSymbolAddress((void**)&hen,  g_hen);
    cudaGetSymbolAddress((void**)&hde,  g_hde);
    cudaGetSymbolAddress((void**)&buf1, g_buf1);
    cudaGetSymbolAddress((void**)&buf2, g_buf2);
    cudaGetSymbolAddress((void**)&lat,  g_lat);
    cudaGetSymbolAddress((void**)&buf3, g_buf3);
    cudaGetSymbolAddress((void**)&buf4, g_buf4);
    cudaGetSymbolAddress((void**)&part, g_part);

    // hypernet hidden states for encoder + decoder
    hyper_kernel<<<2, 256>>>(mu, enW0, enb0, enW1, enb1, deW0, deb0, deW1, deb1);

    // encoder: 2000 -> 200 (linear, K split 8 for SM balance), 200 -> 100 (tanh), 100 -> 10 (linear)
    fc_kernel<<<dim3(200, 8), 256>>>(z,    enW2, enb2, hen, part, nullptr,       2000, 200, 0L,      8, 0);
    reduce_kernel<<<(12800 + 255) / 256, 256>>>(part, buf1, 12800, 8);
    fc_kernel<<<dim3(100, 1), 256>>>(buf1, enW2, enb2, hen, buf2, nullptr,       200,  100, 400200L, 1, 1);
    fc_kernel<<<dim3(10, 1),  256>>>(buf2, enW2, enb2, hen, lat,  out + 128000,  100,  10,  420300L, 1, 0);

    // decoder: 10 -> 100 (linear), 100 -> 200 (tanh), 200 -> 2000 (linear, straight to d_out)
    fc_kernel<<<dim3(100, 1),  256>>>(lat,  deW2, deb2, hde, buf3, nullptr,      10,   100, 0L,      1, 0);
    fc_kernel<<<dim3(200, 1),  256>>>(buf3, deW2, deb2, hde, buf4, nullptr,      100,  200, 1100L,   1, 1);
    fc_kernel<<<dim3(2000, 1), 256>>>(buf4, deW2, deb2, hde, out,  nullptr,      200,  2000, 21300L, 1, 0);
}

// round 4
// speedup vs baseline: 1.7329x; 1.7329x over previous
#include <cuda_runtime.h>
#include <cuda_bf16.h>
#include <cstdint>
#include <math.h>

// ================= scratch (device globals: no allocation allowed) =================
__device__ __align__(16) float g_hen[64 * 64];
__device__ __align__(16) float g_hde[64 * 64];
__device__ __align__(16) float g_zT [2000 * 64];
__device__ __align__(16) float g_b1T[200 * 64];
__device__ __align__(16) float g_b2T[100 * 64];
__device__ __align__(16) float g_latT[10 * 64];
__device__ __align__(16) float g_b3T[100 * 64];
__device__ __align__(16) float g_b4T[200 * 64];
__device__ __align__(16) float g_part[11 * 200 * 64];

// ================= helpers =================
__device__ __forceinline__ uint32_t smem_u32(const void* p) {
    uint32_t a;
    asm("{ .reg .u64 t; cvta.to.shared.u64 t, %1; cvt.u32.u64 %0, t; }" : "=r"(a) : "l"(p));
    return a;
}
__device__ __forceinline__ void ldsm_x4(uint32_t* r, uint32_t addr) {
    asm volatile("ldmatrix.sync.aligned.m8n8.x4.shared.b16 {%0,%1,%2,%3}, [%4];"
        : "=r"(r[0]), "=r"(r[1]), "=r"(r[2]), "=r"(r[3]) : "r"(addr));
}
__device__ __forceinline__ void ldsm_x2(uint32_t* r, uint32_t addr) {
    asm volatile("ldmatrix.sync.aligned.m8n8.x2.shared.b16 {%0,%1}, [%2];"
        : "=r"(r[0]), "=r"(r[1]) : "r"(addr));
}
__device__ __forceinline__ void mma_bf16(float* d, const uint32_t* a, const uint32_t* b) {
    asm volatile("mma.sync.aligned.m16n8k16.row.col.f32.bf16.bf16.f32 "
        "{%0,%1,%2,%3}, {%4,%5,%6,%7}, {%8,%9}, {%0,%1,%2,%3};"
        : "+f"(d[0]), "+f"(d[1]), "+f"(d[2]), "+f"(d[3])
        : "r"(a[0]), "r"(a[1]), "r"(a[2]), "r"(a[3]), "r"(b[0]), "r"(b[1]));
}
__device__ __forceinline__ uint32_t packbf(float x, float y) {
    __nv_bfloat162 t = __floats2bfloat162_rn(x, y);
    return *(uint32_t*)&t;
}

// ---- smem byte offsets ----
// HS_HI [64][72]bf16 @0 (9216), HS_LO @9216 (9216), XS float[128][68] @18432 (34816),
// WS 2buf x {hi,lo} [128][72]bf16 @53248 (2*36864), B2S float[2][128] @126976 (1024),
// RED float[5][64] @128000 (1280)  => total 129280
#define OFF_HSL 9216
#define OFF_XS  18432
#define OFF_WS  53248
#define OFF_B2S 126976
#define OFF_RED 128000
#define SM_TOTAL 129280

__device__ __forceinline__ void store_w(char* smem, int buf, int r, int q, float4 v) {
    __nv_bfloat16 hx = __float2bfloat16_rn(v.x);
    __nv_bfloat16 hy = __float2bfloat16_rn(v.y);
    __nv_bfloat16 hz = __float2bfloat16_rn(v.z);
    __nv_bfloat16 hw = __float2bfloat16_rn(v.w);
    uint2 H, L;
    { __nv_bfloat162 t0 = __halves2bfloat162(hx, hy); H.x = *(uint32_t*)&t0;
      __nv_bfloat162 t1 = __halves2bfloat162(hz, hw); H.y = *(uint32_t*)&t1; }
    L.x = packbf(v.x - __bfloat162float(hx), v.y - __bfloat162float(hy));
    L.y = packbf(v.z - __bfloat162float(hz), v.w - __bfloat162float(hw));
    char* p = smem + OFF_WS + buf * 36864 + r * 144 + q * 8;
    *(uint2*)p = H;
    *(uint2*)(p + 18432) = L;
}

// ================= hypernet first two layers =================
__global__ __launch_bounds__(256) void hyper_kernel(
    const float* __restrict__ mu,
    const float* __restrict__ enW0, const float* __restrict__ enb0,
    const float* __restrict__ enW1, const float* __restrict__ enb1,
    const float* __restrict__ deW0, const float* __restrict__ deb0,
    const float* __restrict__ deW1, const float* __restrict__ deb1)
{
    const float* W0; const float* b0; const float* W1; const float* b1; float* H;
    if (blockIdx.x == 0) { W0 = enW0; b0 = enb0; W1 = enW1; b1 = enb1; H = g_hen; }
    else                 { W0 = deW0; b0 = deb0; W1 = deW1; b1 = deb1; H = g_hde; }

    __shared__ float mus[256];
    __shared__ float h1[64][65];
    int tid = threadIdx.x;
    mus[tid] = mu[tid];
    __syncthreads();
    for (int idx = tid; idx < 4096; idx += 256) {
        int b = idx >> 6, o = idx & 63;
        float s = b0[o];
#pragma unroll
        for (int j = 0; j < 4; j++) s += mus[b * 4 + j] * W0[o * 4 + j];
        h1[b][o] = tanhf(s);
    }
    __syncthreads();
    for (int idx = tid; idx < 4096; idx += 256) {
        int b = idx >> 6, o = idx & 63;
        float s = b1[o];
#pragma unroll
        for (int k = 0; k < 64; k++) s += h1[b][k] * W1[o * 64 + k];
        H[b * 64 + o] = tanhf(s);
    }
}

// ================= transpose z: zT[i*64+b] = z[b*ni+i] =================
__global__ void tr_kernel(const float* __restrict__ in, float* __restrict__ outT, int ni)
{
    int idx = blockIdx.x * 256 + threadIdx.x;
    if (idx < ni * 64) {
        int i = idx >> 6, b = idx & 63;
        outT[idx] = in[b * ni + i];
    }
}

// ================= split reduce (+opt tanh, +opt row-major out) =================
__global__ void reduce_kernel(const float* __restrict__ part, float* __restrict__ outT,
                              float* __restrict__ out, int ostride, int n, int s, int do_tanh)
{
    int i = blockIdx.x * 256 + threadIdx.x;
    if (i < n) {
        float v = 0.f;
        for (int j = 0; j < s; j++) v += part[(long)j * n + i];
        if (do_tanh) v = tanhf(v);
        if (outT) outT[i] = v;
        if (out) { int c = i >> 6, b = i & 63; out[b * ostride + c] = v; }
    }
}

// ================= fused hyper-FC layer via mma.sync (HMMA) =================
// Block: NC channels x one K-split. Per chunk of up to 128 j-rows:
//   D[j, b] = W2rows @ h^T  (3-term bf16 split, fp32 acc)
//   acc[b,c] += sum_j (D[j,b] + b2[j]) * x'[j,b]     (x'[ni]=1 folds bias row)
__global__ void __launch_bounds__(256, 1) hfc(
    const float* __restrict__ W2, const float* __restrict__ b2,
    const float* __restrict__ xT, const float* __restrict__ hsrc,
    float* __restrict__ outT, float* __restrict__ out, int ostride,
    int ni, int no, long off, int NC, int nsplit, int do_tanh,
    float* __restrict__ part)
{
    extern __shared__ __align__(16) char smem[];
    const int tid = threadIdx.x, lane = tid & 31, wid = tid >> 5;
    const int wn = wid & 3, wm = wid >> 2;
    const int grp = blockIdx.x / nsplit, split = blockIdx.x % nsplit;
    const int c0 = grp * NC;
    const int K1 = ni + 1;
    const int ilen = (K1 + nsplit - 1) / nsplit;
    const int ibeg = split * ilen;
    const int iend = min(ibeg + ilen, K1);
    const uint32_t smb = smem_u32(smem);

    __nv_bfloat16* hsH = (__nv_bfloat16*)(smem);
    __nv_bfloat16* hsL = (__nv_bfloat16*)(smem + OFF_HSL);
    float* xs  = (float*)(smem + OFF_XS);
    float* b2s = (float*)(smem + OFF_B2S);
    float* red = (float*)(smem + OFF_RED);

    // ---- prologue: stage h hi/lo, build B fragments (kept in regs whole kernel) ----
    for (int e = tid; e < 4096; e += 256) {
        int b = e >> 6, k = e & 63;
        float f = hsrc[e];
        __nv_bfloat16 hi = __float2bfloat16_rn(f);
        __nv_bfloat16 lo = __float2bfloat16_rn(f - __bfloat162float(hi));
        hsH[b * 72 + k] = hi;
        hsL[b * 72 + k] = lo;
    }
    __syncthreads();

    uint32_t bh[2][4][2], bl[2][4][2];
    {
        int l2 = lane & 15;
        int rrow = l2 & 7, rsel = l2 >> 3;
#pragma unroll
        for (int nt = 0; nt < 2; nt++) {
            int bb = wn * 16 + nt * 8 + rrow;
#pragma unroll
            for (int ks = 0; ks < 4; ks++) {
                uint32_t aH = smb + (uint32_t)(bb * 144 + ks * 32 + rsel * 16);
                ldsm_x2(bh[nt][ks], aH);
                ldsm_x2(bl[nt][ks], aH + OFF_HSL);
            }
        }
    }

    float acc[5][4];
#pragma unroll
    for (int i = 0; i < 5; i++) { acc[i][0] = acc[i][1] = acc[i][2] = acc[i][3] = 0.f; }

    for (int i0 = ibeg; i0 < iend; i0 += 128) {
        const int rows = min(128, iend - i0);
        const int mt16 = ((rows + 15) >> 4) << 4;
        const int mtiles = mt16 >> 4;
        __syncthreads();

        // ---- stage x chunk (zero-padded; row ni -> 1.0) ----
#pragma unroll
        for (int t = 0; t < 8; t++) {
            int f4 = t * 256 + tid;
            int r = f4 >> 4, q = f4 & 15;
            if (r < mt16) {
                float4 v = make_float4(0.f, 0.f, 0.f, 0.f);
                int gi = i0 + r;
                if (r < rows) {
                    if (gi < ni) v = *(const float4*)(xT + (long)gi * 64 + q * 4);
                    else         v = make_float4(1.f, 1.f, 1.f, 1.f);
                }
                *(float4*)(xs + r * 68 + q * 4) = v;
            }
        }
        // ---- stage W for channel 0 into buf 0 ----
        {
            long wbase = off + (long)c0 * ni;
            long brow  = off + (long)ni * no + c0;
#pragma unroll
            for (int t = 0; t < 8; t++) {
                int f4 = t * 256 + tid;
                int r = f4 >> 4, q = f4 & 15;
                if (r < mt16) {
                    float4 v = make_float4(0.f, 0.f, 0.f, 0.f);
                    int gi = i0 + r;
                    if (r < rows) v = *(const float4*)(W2 + ((gi < ni) ? (wbase + gi) : brow) * 64 + q * 4);
                    store_w(smem, 0, r, q, v);
                }
            }
            if (tid < 128) {
                float bv = 0.f;
                int gi = i0 + tid;
                if (tid < rows) bv = b2[(gi < ni) ? (wbase + gi) : brow];
                b2s[tid] = bv;
            }
        }
        __syncthreads();

#pragma unroll
        for (int ch = 0; ch < 5; ch++) {
            if (ch < NC) {
                const int buf = ch & 1;
                // prefetch next channel's W into regs (overlaps HMMA below)
                float4 wreg[8];
                float bpre = 0.f;
                const bool pf = (ch + 1 < NC);
                if (pf) {
                    long wbase = off + (long)(c0 + ch + 1) * ni;
                    long brow  = off + (long)ni * no + (c0 + ch + 1);
#pragma unroll
                    for (int t = 0; t < 8; t++) {
                        int f4 = t * 256 + tid;
                        int r = f4 >> 4, q = f4 & 15;
                        wreg[t] = make_float4(0.f, 0.f, 0.f, 0.f);
                        if (r < rows) {
                            int gi = i0 + r;
                            wreg[t] = *(const float4*)(W2 + ((gi < ni) ? (wbase + gi) : brow) * 64 + q * 4);
                        }
                    }
                    if (tid < 128 && tid < rows) {
                        int gi = i0 + tid;
                        bpre = b2[(gi < ni) ? (wbase + gi) : brow];
                    }
                }
                // ---- MMA + epilogue on this channel's tiles ----
                const uint32_t wb = smb + OFF_WS + buf * 36864;
                for (int mt = wm; mt < mtiles; mt += 2) {
                    float d[2][4] = {{0.f,0.f,0.f,0.f},{0.f,0.f,0.f,0.f}};
#pragma unroll
                    for (int ks = 0; ks < 4; ks++) {
                        uint32_t aH[4], aL[4];
                        int mat = lane >> 3;
                        int arow = mt * 16 + (lane & 7) + (mat & 1) * 8;
                        uint32_t ad = wb + (uint32_t)(arow * 144 + ks * 32 + (mat >> 1) * 16);
                        ldsm_x4(aH, ad);
                        ldsm_x4(aL, ad + 18432);
#pragma unroll
                        for (int nt = 0; nt < 2; nt++) {
                            mma_bf16(d[nt], aH, bh[nt][ks]);
                            mma_bf16(d[nt], aH, bl[nt][ks]);
                            mma_bf16(d[nt], aL, bh[nt][ks]);
                        }
                    }
                    int jl = mt * 16 + (lane >> 2);
                    float bb0 = b2s[buf * 128 + jl];
                    float bb1 = b2s[buf * 128 + jl + 8];
#pragma unroll
                    for (int nt = 0; nt < 2; nt++) {
                        int col = wn * 16 + nt * 8 + ((lane & 3) << 1);
                        float2 x0 = *(const float2*)(xs + jl * 68 + col);
                        float2 x1 = *(const float2*)(xs + (jl + 8) * 68 + col);
                        acc[ch][nt * 2 + 0] += (d[nt][0] + bb0) * x0.x + (d[nt][2] + bb1) * x1.x;
                        acc[ch][nt * 2 + 1] += (d[nt][1] + bb0) * x0.y + (d[nt][3] + bb1) * x1.y;
                    }
                }
                // commit prefetched W to the other buffer
                if (pf) {
#pragma unroll
                    for (int t = 0; t < 8; t++) {
                        int f4 = t * 256 + tid;
                        int r = f4 >> 4, q = f4 & 15;
                        if (r < mt16) store_w(smem, buf ^ 1, r, q, wreg[t]);
                    }
                    if (tid < 128) b2s[(buf ^ 1) * 128 + tid] = bpre;
                }
                __syncthreads();
            }
        }
    }

    // ---- reduction: lanes (over j-groups) then warp pairs (wm) ----
#pragma unroll
    for (int ch = 0; ch < 5; ch++) {
#pragma unroll
        for (int e = 0; e < 4; e++) {
            float v = acc[ch][e];
            v += __shfl_xor_sync(0xffffffff, v, 4);
            v += __shfl_xor_sync(0xffffffff, v, 8);
            v += __shfl_xor_sync(0xffffffff, v, 16);
            acc[ch][e] = v;
        }
    }
    __syncthreads();
    if (wm == 1 && lane < 4) {
#pragma unroll
        for (int ch = 0; ch < 5; ch++) if (ch < NC) {
#pragma unroll
            for (int nt = 0; nt < 2; nt++)
#pragma unroll
            for (int e = 0; e < 2; e++) {
                int col = wn * 16 + nt * 8 + lane * 2 + e;
                red[ch * 64 + col] = acc[ch][nt * 2 + e];
            }
        }
    }
    __syncthreads();
    if (wm == 0 && lane < 4) {
#pragma unroll
        for (int ch = 0; ch < 5; ch++) if (ch < NC) {
            int cc = c0 + ch;
#pragma unroll
            for (int nt = 0; nt < 2; nt++)
#pragma unroll
            for (int e = 0; e < 2; e++) {
                int col = wn * 16 + nt * 8 + lane * 2 + e;
                float v = acc[ch][nt * 2 + e] + red[ch * 64 + col];
                if (part) {
                    part[(long)split * (no * 64) + (long)cc * 64 + col] = v;
                } else {
                    if (do_tanh) v = tanhf(v);
                    if (outT) outT[(long)cc * 64 + col] = v;
                    if (out)  out[(long)col * ostride + cc] = v;
                }
            }
        }
    }
}

extern "C" void kernel_launch(void* const* d_in, const int* in_sizes, int n_in,
                              void* d_out, int out_size)
{
    const float* z    = (const float*)d_in[0];
    const float* mu   = (const float*)d_in[1];
    const float* enW0 = (const float*)d_in[2];
    const float* enb0 = (const float*)d_in[3];
    const float* enW1 = (const float*)d_in[4];
    const float* enb1 = (const float*)d_in[5];
    const float* enW2 = (const float*)d_in[6];
    const float* enb2 = (const float*)d_in[7];
    const float* deW0 = (const float*)d_in[8];
    const float* deb0 = (const float*)d_in[9];
    const float* deW1 = (const float*)d_in[10];
    const float* deb1 = (const float*)d_in[11];
    const float* deW2 = (const float*)d_in[12];
    const float* deb2 = (const float*)d_in[13];
    float* out = (float*)d_out;

    float *hen, *hde, *zT, *b1T, *b2T, *latT, *b3T, *b4T, *part;
    cudaGetSymbolAddress((void**)&hen,  g_hen);
    cudaGetSymbolAddress((void**)&hde,  g_hde);
    cudaGetSymbolAddress((void**)&zT,   g_zT);
    cudaGetSymbolAddress((void**)&b1T,  g_b1T);
    cudaGetSymbolAddress((void**)&b2T,  g_b2T);
    cudaGetSymbolAddress((void**)&latT, g_latT);
    cudaGetSymbolAddress((void**)&b3T,  g_b3T);
    cudaGetSymbolAddress((void**)&b4T,  g_b4T);
    cudaGetSymbolAddress((void**)&part, g_part);

    cudaFuncSetAttribute(hfc, cudaFuncAttributeMaxDynamicSharedMemorySize, SM_TOTAL);

    hyper_kernel<<<2, 256>>>(mu, enW0, enb0, enW1, enb1, deW0, deb0, deW1, deb1);
    tr_kernel<<<500, 256>>>(z, zT, 2000);

    // encoder L0: 2000 -> 200, linear, NC=5, 11 K-splits (grid 440 ~ 3 waves)
    hfc<<<440, 256, SM_TOTAL>>>(enW2, enb2, zT, hen, nullptr, nullptr, 0,
                                2000, 200, 0L, 5, 11, 0, part);
    reduce_kernel<<<50, 256>>>(part, b1T, nullptr, 0, 12800, 11, 0);
    // encoder L1: 200 -> 100, tanh, NC=5, 7 splits (grid 140)
    hfc<<<140, 256, SM_TOTAL>>>(enW2, enb2, b1T, hen, nullptr, nullptr, 0,
                                200, 100, 400200L, 5, 7, 0, part);
    reduce_kernel<<<25, 256>>>(part, b2T, nullptr, 0, 6400, 7, 1);
    // encoder L2: 100 -> 10, linear, NC=2, 13 splits (grid 65); latent -> latT + d_out tail
    hfc<<<65, 256, SM_TOTAL>>>(enW2, enb2, b2T, hen, nullptr, nullptr, 0,
                               100, 10, 420300L, 2, 13, 0, part);
    reduce_kernel<<<3, 256>>>(part, latT, out + 128000, 10, 640, 13, 0);

    // decoder L0: 10 -> 100, linear, NC=1 (grid 100)
    hfc<<<100, 256, SM_TOTAL>>>(deW2, deb2, latT, hde, b3T, nullptr, 0,
                                10, 100, 0L, 1, 1, 0, nullptr);
    // decoder L1: 100 -> 200, tanh, NC=5, 3 splits (grid 120)
    hfc<<<120, 256, SM_TOTAL>>>(deW2, deb2, b3T, hde, nullptr, nullptr, 0,
                                100, 200, 1100L, 5, 3, 0, part);
    reduce_kernel<<<50, 256>>>(part, b4T, nullptr, 0, 12800, 3, 1);
    // decoder L2: 200 -> 2000, linear, NC=5 (grid 400), straight to d_out
    hfc<<<400, 256, SM_TOTAL>>>(deW2, deb2, b4T, hde, nullptr, out, 2000,
                                200, 2000, 21300L, 5, 1, 0, nullptr);
}

// round 5
// speedup vs baseline: 1.8395x; 1.0615x over previous
#include <cuda_runtime.h>
#include <cuda_bf16.h>
#include <cstdint>
#include <math.h>

// ================= scratch (device globals: no allocation allowed) =================
__device__ __align__(16) float g_hen[64 * 64];
__device__ __align__(16) float g_hde[64 * 64];
__device__ __align__(16) float g_zT [2000 * 64];
__device__ __align__(16) float g_b1T[200 * 64];
__device__ __align__(16) float g_b2T[100 * 64];
__device__ __align__(16) float g_latT[10 * 64];
__device__ __align__(16) float g_b3T[100 * 64];
__device__ __align__(16) float g_b4T[200 * 64];
__device__ __align__(16) float g_part[16 * 200 * 64];

// ================= helpers =================
__device__ __forceinline__ uint32_t smem_u32(const void* p) {
    uint32_t a;
    asm("{ .reg .u64 t; cvta.to.shared.u64 t, %1; cvt.u32.u64 %0, t; }" : "=r"(a) : "l"(p));
    return a;
}
__device__ __forceinline__ void ldsm_x2(uint32_t* r, uint32_t addr) {
    asm volatile("ldmatrix.sync.aligned.m8n8.x2.shared.b16 {%0,%1}, [%2];"
        : "=r"(r[0]), "=r"(r[1]) : "r"(addr));
}
__device__ __forceinline__ void mma_bf16(float* d, const uint32_t* a, const uint32_t* b) {
    asm volatile("mma.sync.aligned.m16n8k16.row.col.f32.bf16.bf16.f32 "
        "{%0,%1,%2,%3}, {%4,%5,%6,%7}, {%8,%9}, {%0,%1,%2,%3};"
        : "+f"(d[0]), "+f"(d[1]), "+f"(d[2]), "+f"(d[3])
        : "r"(a[0]), "r"(a[1]), "r"(a[2]), "r"(a[3]), "r"(b[0]), "r"(b[1]));
}
// pack hi16 halves of (a,b) -> bf16x2 {low=a_hi16, high=b_hi16}  (truncating bf16 split)
__device__ __forceinline__ uint32_t prmt_hi(float a, float b) {
    uint32_t r;
    asm("prmt.b32 %0, %1, %2, 0x7632;"
        : "=r"(r) : "r"(__float_as_uint(a)), "r"(__float_as_uint(b)));
    return r;
}
// residual after truncating hi split, packed to bf16x2 {low=resid(a), high=resid(b)}
__device__ __forceinline__ uint32_t pack_lo_resid(float a, float b) {
    float la = a - __uint_as_float(__float_as_uint(a) & 0xffff0000u);
    float lb = b - __uint_as_float(__float_as_uint(b) & 0xffff0000u);
    uint32_t r;
    asm("cvt.rn.bf16x2.f32 %0, %1, %2;" : "=r"(r) : "f"(lb), "f"(la));
    return r;
}

// ================= hypernet (blocks 0,1) + z transpose (blocks 2..) =================
__global__ __launch_bounds__(256) void hyper_tr(
    const float* __restrict__ mu,
    const float* __restrict__ enW0, const float* __restrict__ enb0,
    const float* __restrict__ enW1, const float* __restrict__ enb1,
    const float* __restrict__ deW0, const float* __restrict__ deb0,
    const float* __restrict__ deW1, const float* __restrict__ deb1,
    const float* __restrict__ z)
{
    int tid = threadIdx.x;
    if (blockIdx.x >= 2) {
        int idx = (blockIdx.x - 2) * 256 + tid;
        if (idx < 2000 * 64) {
            int i = idx >> 6, b = idx & 63;
            g_zT[idx] = z[b * 2000 + i];
        }
        return;
    }
    const float* W0; const float* b0; const float* W1; const float* b1; float* H;
    if (blockIdx.x == 0) { W0 = enW0; b0 = enb0; W1 = enW1; b1 = enb1; H = g_hen; }
    else                 { W0 = deW0; b0 = deb0; W1 = deW1; b1 = deb1; H = g_hde; }

    __shared__ float mus[256];
    __shared__ float h1[64][65];
    mus[tid] = mu[tid];
    __syncthreads();
    for (int idx = tid; idx < 4096; idx += 256) {
        int b = idx >> 6, o = idx & 63;
        float s = b0[o];
#pragma unroll
        for (int j = 0; j < 4; j++) s += mus[b * 4 + j] * W0[o * 4 + j];
        h1[b][o] = tanhf(s);
    }
    __syncthreads();
    for (int idx = tid; idx < 4096; idx += 256) {
        int b = idx >> 6, o = idx & 63;
        float s = b1[o];
#pragma unroll
        for (int k = 0; k < 64; k++) s += h1[b][k] * W1[o * 64 + k];
        H[b * 64 + o] = tanhf(s);
    }
}

// ================= split reduce (+opt tanh, +opt row-major copy) =================
__global__ void reduce_kernel(const float* __restrict__ part, float* __restrict__ outT,
                              float* __restrict__ out, int ostride, int n, int s, int do_tanh)
{
    int i = blockIdx.x * 256 + threadIdx.x;
    if (i < n) {
        float v = 0.f;
        for (int j = 0; j < s; j++) v += part[(long)j * n + i];
        if (do_tanh) v = tanhf(v);
        if (outT) outT[i] = v;
        if (out) { int c = i >> 6, b = i & 63; out[b * ostride + c] = v; }
    }
}

// ================= fused hyper-FC layer: direct-LDG HMMA =================
// Team (4 warps, n-col split) owns one channel cc within one K-split.
// Per 16-row tile:  D[j,b] = W2rows @ h^T (3-term bf16 split, fp32 acc)
//   acc[b] += sum_j (D[j,b] + b2[j]) * x'[j,b]   (x'[ni] = 1 folds the layer bias)
__global__ void __launch_bounds__(256) hfc2(
    const float* __restrict__ W2, const float* __restrict__ b2,
    const float* __restrict__ xT, const float* __restrict__ hsrc,
    float* __restrict__ outT, float* __restrict__ out, int ostride,
    int ni, int no, long off, int nsplit, int do_tanh, float* __restrict__ part)
{
    __shared__ __align__(16) __nv_bfloat16 hsH[64 * 72];
    __shared__ __align__(16) __nv_bfloat16 hsL[64 * 72];

    const int tid = threadIdx.x, lane = tid & 31, wid = tid >> 5;
    const int wn = wid & 3, team = wid >> 2;
    const int grp = blockIdx.x / nsplit, split = blockIdx.x % nsplit;
    const int cc = grp * 2 + team;
    const int K1 = ni + 1;
    const int ilen = (K1 + nsplit - 1) / nsplit;
    const int ibeg = split * ilen;
    const int iend = min(ibeg + ilen, K1);
    const int ntiles = (iend - ibeg + 15) >> 4;
    const long wbase = off + (long)cc * ni;
    const long brow  = off + (long)ni * no + cc;

    // ---- prologue: stage h (RN hi/lo split), build B fragments, then NO more syncs ----
    for (int e = tid; e < 4096; e += 256) {
        float f = hsrc[e];
        __nv_bfloat16 hi = __float2bfloat16_rn(f);
        __nv_bfloat16 lo = __float2bfloat16_rn(f - __bfloat162float(hi));
        int b = e >> 6, k = e & 63;
        hsH[b * 72 + k] = hi;
        hsL[b * 72 + k] = lo;
    }
    __syncthreads();

    const uint32_t smbH = smem_u32(hsH), smbL = smem_u32(hsL);
    uint32_t bh[2][4][2], bl[2][4][2];
    {
        int l2 = lane & 15, rrow = l2 & 7, rsel = l2 >> 3;
#pragma unroll
        for (int nt = 0; nt < 2; nt++) {
            int bb = wn * 16 + nt * 8 + rrow;
#pragma unroll
            for (int ks = 0; ks < 4; ks++) {
                uint32_t o_ = (uint32_t)(bb * 144 + ks * 32 + rsel * 16);
                ldsm_x2(bh[nt][ks], smbH + o_);
                ldsm_x2(bl[nt][ks], smbL + o_);
            }
        }
    }

    float acc[4] = {0.f, 0.f, 0.f, 0.f};
    const int cbase = (lane & 3) * 2;
    const float2 z2 = make_float2(0.f, 0.f);

    for (int mt = 0; mt < ntiles; ++mt) {
        const int g0 = ibeg + mt * 16 + (lane >> 2);
        const int g1 = g0 + 8;
        const bool v0 = g0 < iend, v1 = g1 < iend;
        const long r0 = (g0 < ni) ? (wbase + g0) : brow;
        const long r1 = (g1 < ni) ? (wbase + g1) : brow;
        const float* p0 = W2 + r0 * 64 + cbase;
        const float* p1 = W2 + r1 * 64 + cbase;

        // ---- batched independent loads (22 LDGs in flight) ----
        float2 w[4][4];
#pragma unroll
        for (int ks = 0; ks < 4; ks++) {
            w[ks][0] = v0 ? *(const float2*)(p0 + ks * 16)     : z2;
            w[ks][1] = v1 ? *(const float2*)(p1 + ks * 16)     : z2;
            w[ks][2] = v0 ? *(const float2*)(p0 + ks * 16 + 8) : z2;
            w[ks][3] = v1 ? *(const float2*)(p1 + ks * 16 + 8) : z2;
        }
        const float bb0 = v0 ? b2[r0] : 0.f;
        const float bb1 = v1 ? b2[r1] : 0.f;
        float2 x0[2], x1[2];
#pragma unroll
        for (int nt = 0; nt < 2; nt++) {
            int col = wn * 16 + nt * 8 + cbase;
            x0[nt] = v0 ? (g0 < ni ? *(const float2*)(xT + (long)g0 * 64 + col) : make_float2(1.f, 1.f)) : z2;
            x1[nt] = v1 ? (g1 < ni ? *(const float2*)(xT + (long)g1 * 64 + col) : make_float2(1.f, 1.f)) : z2;
        }

        // ---- convert + MMA (3-term split) ----
        float d[2][4] = {{0.f,0.f,0.f,0.f},{0.f,0.f,0.f,0.f}};
#pragma unroll
        for (int ks = 0; ks < 4; ks++) {
            uint32_t aH[4], aL[4];
#pragma unroll
            for (int p = 0; p < 4; p++) {
                aH[p] = prmt_hi(w[ks][p].x, w[ks][p].y);
                aL[p] = pack_lo_resid(w[ks][p].x, w[ks][p].y);
            }
#pragma unroll
            for (int nt = 0; nt < 2; nt++) {
                mma_bf16(d[nt], aH, bh[nt][ks]);
                mma_bf16(d[nt], aH, bl[nt][ks]);
                mma_bf16(d[nt], aL, bh[nt][ks]);
            }
        }
        // ---- register epilogue ----
#pragma unroll
        for (int nt = 0; nt < 2; nt++) {
            acc[nt * 2 + 0] += (d[nt][0] + bb0) * x0[nt].x + (d[nt][2] + bb1) * x1[nt].x;
            acc[nt * 2 + 1] += (d[nt][1] + bb0) * x0[nt].y + (d[nt][3] + bb1) * x1[nt].y;
        }
    }

    // ---- warp-shuffle reduce over j-groups (lane bits 2..4), then write ----
#pragma unroll
    for (int e = 0; e < 4; e++) {
        acc[e] += __shfl_xor_sync(0xffffffffu, acc[e], 4);
        acc[e] += __shfl_xor_sync(0xffffffffu, acc[e], 8);
        acc[e] += __shfl_xor_sync(0xffffffffu, acc[e], 16);
    }
    if (lane < 4) {
#pragma unroll
        for (int nt = 0; nt < 2; nt++)
#pragma unroll
        for (int e2 = 0; e2 < 2; e2++) {
            int col = wn * 16 + nt * 8 + lane * 2 + e2;
            float v = acc[nt * 2 + e2];
            if (part) {
                part[(long)split * (no * 64) + (long)cc * 64 + col] = v;
            } else {
                if (do_tanh) v = tanhf(v);
                if (outT) outT[(long)cc * 64 + col] = v;
                if (out)  out[(long)col * ostride + cc] = v;
            }
        }
    }
}

extern "C" void kernel_launch(void* const* d_in, const int* in_sizes, int n_in,
                              void* d_out, int out_size)
{
    const float* z    = (const float*)d_in[0];
    const float* mu   = (const float*)d_in[1];
    const float* enW0 = (const float*)d_in[2];
    const float* enb0 = (const float*)d_in[3];
    const float* enW1 = (const float*)d_in[4];
    const float* enb1 = (const float*)d_in[5];
    const float* enW2 = (const float*)d_in[6];
    const float* enb2 = (const float*)d_in[7];
    const float* deW0 = (const float*)d_in[8];
    const float* deb0 = (const float*)d_in[9];
    const float* deW1 = (const float*)d_in[10];
    const float* deb1 = (const float*)d_in[11];
    const float* deW2 = (const float*)d_in[12];
    const float* deb2 = (const float*)d_in[13];
    float* out = (float*)d_out;

    float *hen, *hde, *zT, *b1T, *b2T, *latT, *b3T, *b4T, *part;
    cudaGetSymbolAddress((void**)&hen,  g_hen);
    cudaGetSymbolAddress((void**)&hde,  g_hde);
    cudaGetSymbolAddress((void**)&zT,   g_zT);
    cudaGetSymbolAddress((void**)&b1T,  g_b1T);
    cudaGetSymbolAddress((void**)&b2T,  g_b2T);
    cudaGetSymbolAddress((void**)&latT, g_latT);
    cudaGetSymbolAddress((void**)&b3T,  g_b3T);
    cudaGetSymbolAddress((void**)&b4T,  g_b4T);
    cudaGetSymbolAddress((void**)&part, g_part);

    // hypernet hidden states + z transpose in one launch
    hyper_tr<<<502, 256>>>(mu, enW0, enb0, enW1, enb1, deW0, deb0, deW1, deb1, z);

    // encoder L0: 2000 -> 200, linear, 3 K-splits (grid 300 = ~2 waves)
    hfc2<<<300, 256>>>(enW2, enb2, zT, hen, nullptr, nullptr, 0,
                       2000, 200, 0L, 3, 0, part);
    reduce_kernel<<<50, 256>>>(part, b1T, nullptr, 0, 12800, 3, 0);
    // encoder L1: 200 -> 100, tanh, 6 splits (grid 300)
    hfc2<<<300, 256>>>(enW2, enb2, b1T, hen, nullptr, nullptr, 0,
                       200, 100, 400200L, 6, 0, part);
    reduce_kernel<<<25, 256>>>(part, b2T, nullptr, 0, 6400, 6, 1);
    // encoder L2: 100 -> 10, linear, 7 splits (grid 35); latent -> latT + d_out tail
    hfc2<<<35, 256>>>(enW2, enb2, b2T, hen, nullptr, nullptr, 0,
                      100, 10, 420300L, 7, 0, part);
    reduce_kernel<<<3, 256>>>(part, latT, out + 128000, 10, 640, 7, 0);

    // decoder L0: 10 -> 100, linear (grid 50)
    hfc2<<<50, 256>>>(deW2, deb2, latT, hde, b3T, nullptr, 0,
                      10, 100, 0L, 1, 0, nullptr);
    // decoder L1: 100 -> 200, tanh inline (grid 100)
    hfc2<<<100, 256>>>(deW2, deb2, b3T, hde, b4T, nullptr, 0,
                       100, 200, 1100L, 1, 1, nullptr);
    // decoder L2: 200 -> 2000, linear, straight to d_out (grid 1000 = ~6.8 waves)
    hfc2<<<1000, 256>>>(deW2, deb2, b4T, hde, nullptr, out, 2000,
                        200, 2000, 21300L, 1, 0, nullptr);
}